// round 2
// baseline (speedup 1.0000x reference)
#include <cuda_runtime.h>

#define EMB   768
#define HEADS 12
#define DKH   64
#define BATCH 2
#define SEQ   2048
#define MTOT  (BATCH * SEQ)   // 4096

// ---------------------------------------------------------------------------
// Scratch (allocation-free: __device__ globals)
// ---------------------------------------------------------------------------
__device__ float g_q[MTOT * EMB];
__device__ float g_k[MTOT * EMB];
__device__ float g_v[MTOT * EMB];
__device__ float g_att[MTOT * EMB];

// ---------------------------------------------------------------------------
// GEMM + bias:  C[M,N] = A[M,K] @ W[N,K]^T + b[N]
// Tiles: 64x64, BK=16, 256 threads, 4x4 micro-tile, float4 LDS
// ---------------------------------------------------------------------------
__global__ __launch_bounds__(256) void gemm_bias_kernel(
    const float* __restrict__ A,
    const float* __restrict__ W,
    const float* __restrict__ b,
    float* __restrict__ C,
    int M, int N, int K)
{
    __shared__ __align__(16) float As[16][68];   // [k][m], padded
    __shared__ __align__(16) float Ws[16][68];   // [k][n], padded

    const int t  = threadIdx.x;
    const int tx = t & 15;         // 0..15 -> n
    const int ty = t >> 4;         // 0..15 -> m
    const int m0 = blockIdx.y * 64;
    const int n0 = blockIdx.x * 64;

    const int lm = t >> 2;         // 0..63 row to load
    const int lk = (t & 3) * 4;    // 0,4,8,12 k offset

    float acc[4][4];
#pragma unroll
    for (int i = 0; i < 4; ++i)
#pragma unroll
        for (int j = 0; j < 4; ++j) acc[i][j] = 0.f;

    for (int k0 = 0; k0 < K; k0 += 16) {
        float4 av = *(const float4*)&A[(size_t)(m0 + lm) * K + k0 + lk];
        float4 wv = *(const float4*)&W[(size_t)(n0 + lm) * K + k0 + lk];
        __syncthreads();
        As[lk + 0][lm] = av.x; As[lk + 1][lm] = av.y;
        As[lk + 2][lm] = av.z; As[lk + 3][lm] = av.w;
        Ws[lk + 0][lm] = wv.x; Ws[lk + 1][lm] = wv.y;
        Ws[lk + 2][lm] = wv.z; Ws[lk + 3][lm] = wv.w;
        __syncthreads();

#pragma unroll
        for (int kk = 0; kk < 16; ++kk) {
            float4 a4 = *(const float4*)&As[kk][ty * 4];
            float4 w4 = *(const float4*)&Ws[kk][tx * 4];
            float ar[4] = {a4.x, a4.y, a4.z, a4.w};
            float wr[4] = {w4.x, w4.y, w4.z, w4.w};
#pragma unroll
            for (int i = 0; i < 4; ++i)
#pragma unroll
                for (int j = 0; j < 4; ++j)
                    acc[i][j] += ar[i] * wr[j];
        }
    }

#pragma unroll
    for (int i = 0; i < 4; ++i) {
        const int m = m0 + ty * 4 + i;
#pragma unroll
        for (int j = 0; j < 4; ++j) {
            const int n = n0 + tx * 4 + j;
            C[(size_t)m * N + n] = acc[i][j] + b[n];
        }
    }
}

// ---------------------------------------------------------------------------
// Flash-attention (fp32, online softmax).
// Per block: one (b, h, 64-query tile). 256 threads, 4x4 micro-tiles.
// smem: Qs, Ks, Vs, Ps  each 64x68 floats -> 69632 B dynamic.
// ---------------------------------------------------------------------------
#define AP 68   // padded row stride (floats), multiple of 4 for float4
#define QS(r,c) Qs[(r) * AP + (c)]
#define KS(r,c) Ks[(r) * AP + (c)]
#define VS(r,c) Vs[(r) * AP + (c)]
#define PS(r,c) Ps[(r) * AP + (c)]

__global__ __launch_bounds__(256) void attn_kernel()
{
    extern __shared__ float sm[];
    float* Qs = sm;
    float* Ks = sm + 64 * AP;
    float* Vs = sm + 2 * 64 * AP;
    float* Ps = sm + 3 * 64 * AP;

    const int t   = threadIdx.x;
    const int tx  = t & 15;
    const int ty  = t >> 4;
    const int q0  = blockIdx.x * 64;
    const int h   = blockIdx.y;
    const int bb  = blockIdx.z;

    const size_t base = (size_t)bb * SEQ * EMB + h * DKH;

    // load Q tile: 64 rows x 64 cols
#pragma unroll
    for (int p = 0; p < 4; ++p) {
        const int r = p * 16 + (t >> 4);
        const int d = (t & 15) * 4;
        float4 v = *(const float4*)&g_q[base + (size_t)(q0 + r) * EMB + d];
        QS(r, d + 0) = v.x; QS(r, d + 1) = v.y;
        QS(r, d + 2) = v.z; QS(r, d + 3) = v.w;
    }

    float m_i[4], l_i[4], o[4][4];
#pragma unroll
    for (int i = 0; i < 4; ++i) {
        m_i[i] = -1e30f; l_i[i] = 0.f;
#pragma unroll
        for (int j = 0; j < 4; ++j) o[i][j] = 0.f;
    }

    const int ty4 = ty * 4, tx4 = tx * 4;

    for (int kt = 0; kt < SEQ / 64; ++kt) {
        __syncthreads();   // protect smem reads of previous iter
        // load K, V tiles (64 rows each)
#pragma unroll
        for (int p = 0; p < 4; ++p) {
            const int r = p * 16 + (t >> 4);
            const int d = (t & 15) * 4;
            const size_t g = base + (size_t)(kt * 64 + r) * EMB + d;
            float4 kv = *(const float4*)&g_k[g];
            float4 vv = *(const float4*)&g_v[g];
            KS(r, d + 0) = kv.x; KS(r, d + 1) = kv.y;
            KS(r, d + 2) = kv.z; KS(r, d + 3) = kv.w;
            VS(r, d + 0) = vv.x; VS(r, d + 1) = vv.y;
            VS(r, d + 2) = vv.z; VS(r, d + 3) = vv.w;
        }
        __syncthreads();

        // S = scale * Q K^T  (4x4 per thread)
        float s[4][4];
#pragma unroll
        for (int i = 0; i < 4; ++i)
#pragma unroll
            for (int j = 0; j < 4; ++j) s[i][j] = 0.f;

#pragma unroll 4
        for (int d4 = 0; d4 < 16; ++d4) {
            float4 qv[4], kv[4];
#pragma unroll
            for (int i = 0; i < 4; ++i) qv[i] = *(const float4*)&QS(ty4 + i, d4 * 4);
#pragma unroll
            for (int j = 0; j < 4; ++j) kv[j] = *(const float4*)&KS(tx4 + j, d4 * 4);
#pragma unroll
            for (int i = 0; i < 4; ++i)
#pragma unroll
                for (int j = 0; j < 4; ++j)
                    s[i][j] += qv[i].x * kv[j].x + qv[i].y * kv[j].y
                             + qv[i].z * kv[j].z + qv[i].w * kv[j].w;
        }

        const float scale = 0.125f;   // 1/sqrt(64)
#pragma unroll
        for (int i = 0; i < 4; ++i) {
            float rm = -1e30f;
#pragma unroll
            for (int j = 0; j < 4; ++j) {
                s[i][j] *= scale;
                rm = fmaxf(rm, s[i][j]);
            }
            // reduce max over the 16 lanes sharing this row group
            rm = fmaxf(rm, __shfl_xor_sync(0xffffffffu, rm, 8));
            rm = fmaxf(rm, __shfl_xor_sync(0xffffffffu, rm, 4));
            rm = fmaxf(rm, __shfl_xor_sync(0xffffffffu, rm, 2));
            rm = fmaxf(rm, __shfl_xor_sync(0xffffffffu, rm, 1));

            const float mnew = fmaxf(m_i[i], rm);
            const float corr = __expf(m_i[i] - mnew);
            float rs = 0.f;
#pragma unroll
            for (int j = 0; j < 4; ++j) {
                s[i][j] = __expf(s[i][j] - mnew);   // s becomes P
                rs += s[i][j];
            }
            rs += __shfl_xor_sync(0xffffffffu, rs, 8);
            rs += __shfl_xor_sync(0xffffffffu, rs, 4);
            rs += __shfl_xor_sync(0xffffffffu, rs, 2);
            rs += __shfl_xor_sync(0xffffffffu, rs, 1);

            l_i[i] = l_i[i] * corr + rs;
            m_i[i] = mnew;
#pragma unroll
            for (int j = 0; j < 4; ++j) o[i][j] *= corr;
        }

        // publish P
#pragma unroll
        for (int i = 0; i < 4; ++i)
            *(float4*)&PS(ty4 + i, tx4) = make_float4(s[i][0], s[i][1], s[i][2], s[i][3]);
        __syncthreads();

        // O += P @ V
#pragma unroll 8
        for (int c = 0; c < 64; ++c) {
            float4 v4 = *(const float4*)&VS(c, tx4);
#pragma unroll
            for (int i = 0; i < 4; ++i) {
                const float pv = PS(ty4 + i, c);
                o[i][0] += pv * v4.x;
                o[i][1] += pv * v4.y;
                o[i][2] += pv * v4.z;
                o[i][3] += pv * v4.w;
            }
        }
    }

    // epilogue: normalize and store to g_att (concat layout [B,S,EMB])
#pragma unroll
    for (int i = 0; i < 4; ++i) {
        const float inv = 1.f / l_i[i];
        const size_t row = base + (size_t)(q0 + ty4 + i) * EMB + tx4;
        *(float4*)&g_att[row] = make_float4(o[i][0] * inv, o[i][1] * inv,
                                            o[i][2] * inv, o[i][3] * inv);
    }
}

// ---------------------------------------------------------------------------
// Launch
// ---------------------------------------------------------------------------
extern "C" void kernel_launch(void* const* d_in, const int* in_sizes, int n_in,
                              void* d_out, int out_size)
{
    const float* q  = (const float*)d_in[0];
    const float* k  = (const float*)d_in[1];
    const float* v  = (const float*)d_in[2];
    const float* Wq = (const float*)d_in[3];
    const float* bq = (const float*)d_in[4];
    const float* Wk = (const float*)d_in[5];
    const float* bk = (const float*)d_in[6];
    const float* Wv = (const float*)d_in[7];
    const float* bv = (const float*)d_in[8];
    const float* Wo = (const float*)d_in[9];
    const float* bo = (const float*)d_in[10];
    float* out = (float*)d_out;

    float *gq, *gk, *gv, *ga;
    cudaGetSymbolAddress((void**)&gq, g_q);
    cudaGetSymbolAddress((void**)&gk, g_k);
    cudaGetSymbolAddress((void**)&gv, g_v);
    cudaGetSymbolAddress((void**)&ga, g_att);

    dim3 gb(256);
    dim3 gg(EMB / 64, MTOT / 64);

    gemm_bias_kernel<<<gg, gb>>>(q, Wq, bq, gq, MTOT, EMB, EMB);
    gemm_bias_kernel<<<gg, gb>>>(k, Wk, bk, gk, MTOT, EMB, EMB);
    gemm_bias_kernel<<<gg, gb>>>(v, Wv, bv, gv, MTOT, EMB, EMB);

    const int attn_smem = 4 * 64 * AP * (int)sizeof(float);   // 69632 B
    cudaFuncSetAttribute(attn_kernel, cudaFuncAttributeMaxDynamicSharedMemorySize, attn_smem);
    attn_kernel<<<dim3(SEQ / 64, HEADS, BATCH), 256, attn_smem>>>();

    gemm_bias_kernel<<<gg, gb>>>(ga, Wo, bo, out, MTOT, EMB, EMB);
}

// round 17
// speedup vs baseline: 1.1911x; 1.1911x over previous
#include <cuda_runtime.h>
#include <cstdint>

#define EMB   768
#define HEADS 12
#define DKH   64
#define BATCH 2
#define SEQ   2048
#define MTOT  (BATCH * SEQ)   // 4096

// ---------------------------------------------------------------------------
// Scratch (allocation-free: __device__ globals)
// ---------------------------------------------------------------------------
__device__ float g_q[MTOT * EMB];
__device__ float g_k[MTOT * EMB];
__device__ float g_v[MTOT * EMB];
__device__ float g_att[MTOT * EMB];

// ---------------------------------------------------------------------------
// Baseline-PTX helpers (NO arch-variant features: harness PTX target is
// compute_103 without the 'a' suffix, so tcgen05/TMEM are unavailable).
// ---------------------------------------------------------------------------
__device__ __forceinline__ float f2tf32(float x) {
    uint32_t u;
    asm("cvt.rna.tf32.f32 %0, %1;" : "=r"(u) : "f"(x));
    return __uint_as_float(u);
}

// mma.sync m16n8k8 tf32 (sm_80+ baseline feature) with fp32 accumulate.
__device__ __forceinline__ void mma_tf32(float* c, const uint32_t* a, const uint32_t* b) {
    asm volatile(
        "mma.sync.aligned.m16n8k8.row.col.f32.tf32.tf32.f32 "
        "{%0,%1,%2,%3}, {%4,%5,%6,%7}, {%8,%9}, {%0,%1,%2,%3};"
        : "+f"(c[0]), "+f"(c[1]), "+f"(c[2]), "+f"(c[3])
        : "r"(a[0]), "r"(a[1]), "r"(a[2]), "r"(a[3]), "r"(b[0]), "r"(b[1]));
}

// ===========================================================================
// Tensor-core GEMM + bias:  C[M,768] = A[M,768] @ W[768,768]^T + b
// CTA tile 128x64, BK=32, 256 threads (8 warps, 4x2), warp tile 32x32
// (2 m-frags x 4 n-frags of m16n8k8 tf32).
//
// SMEM k-permutation: element (row, c) stored at [row][ (c&3)*8 + (c>>2) ].
// Then a thread (t4 = lane&3) finds its fragment elements for ALL 4 k-steps
// of BK=32 at [row][t4*8 .. t4*8+7]  ->  two float4 loads per row.
//   k-step ks uses positions p0=2ks (a0/b0: col 8ks+t4) and p1=2ks+1
//   (a2/b1: col 8ks+t4+4).
// ===========================================================================
#define BM   128
#define BN   64
#define BK   32
#define SSTR 36   // padded row stride in floats (16B-aligned rows, no conflicts)

__global__ __launch_bounds__(256) void gemm_mma_kernel(
    const float* __restrict__ A,
    const float* __restrict__ W,
    const float* __restrict__ bias,
    float* __restrict__ C)
{
    __shared__ __align__(16) float As[BM * SSTR];   // 18432 B
    __shared__ __align__(16) float Ws[BN * SSTR];   //  9216 B

    const int tid  = threadIdx.x;
    const int lane = tid & 31;
    const int w    = tid >> 5;           // 0..7
    const int wm   = (w >> 1) * 32;      // warp M base in CTA tile
    const int wn   = (w & 1) * 32;       // warp N base
    const int g    = lane >> 2;          // groupID 0..7
    const int t4   = lane & 3;           // threadID_in_group

    const int m0 = blockIdx.y * BM;
    const int n0 = blockIdx.x * BN;

    float acc[2][4][4];
#pragma unroll
    for (int mf = 0; mf < 2; ++mf)
#pragma unroll
        for (int nf = 0; nf < 4; ++nf)
#pragma unroll
            for (int r = 0; r < 4; ++r) acc[mf][nf][r] = 0.f;

    const int rA[4] = {wm + g, wm + g + 8, wm + g + 16, wm + g + 24};
    const int rB[4] = {wn + g, wn + g + 8, wn + g + 16, wn + g + 24};

    for (int k0 = 0; k0 < EMB; k0 += BK) {
        __syncthreads();
        // ---- load A tile 128x32 (2 threads/row, 4 float4 each), k-permuted
        {
            const int row   = tid >> 1;
            const int cbase = (tid & 1) * 16;
            const float* src = A + (size_t)(m0 + row) * EMB + k0 + cbase;
            float* dst = As + row * SSTR;
#pragma unroll
            for (int j = 0; j < 4; ++j) {
                float4 v = *(const float4*)(src + j * 4);
                const int p = (cbase >> 2) + j;        // (c>>2), c = cbase+4j
                dst[0 * 8 + p] = f2tf32(v.x);
                dst[1 * 8 + p] = f2tf32(v.y);
                dst[2 * 8 + p] = f2tf32(v.z);
                dst[3 * 8 + p] = f2tf32(v.w);
            }
        }
        // ---- load W tile 64x32 (4 threads/row, 2 float4 each), k-permuted
        {
            const int row   = tid >> 2;
            const int cbase = (tid & 3) * 8;
            const float* src = W + (size_t)(n0 + row) * EMB + k0 + cbase;
            float* dst = Ws + row * SSTR;
#pragma unroll
            for (int j = 0; j < 2; ++j) {
                float4 v = *(const float4*)(src + j * 4);
                const int p = (cbase >> 2) + j;
                dst[0 * 8 + p] = f2tf32(v.x);
                dst[1 * 8 + p] = f2tf32(v.y);
                dst[2 * 8 + p] = f2tf32(v.z);
                dst[3 * 8 + p] = f2tf32(v.w);
            }
        }
        __syncthreads();

        // ---- fragment loads: 8 floats per needed row (all 4 k-steps at once)
        float aF[4][8], bF[4][8];
#pragma unroll
        for (int i = 0; i < 4; ++i) {
            const float* s = &As[rA[i] * SSTR + t4 * 8];
            float4 v0 = *(const float4*)s;
            float4 v1 = *(const float4*)(s + 4);
            aF[i][0] = v0.x; aF[i][1] = v0.y; aF[i][2] = v0.z; aF[i][3] = v0.w;
            aF[i][4] = v1.x; aF[i][5] = v1.y; aF[i][6] = v1.z; aF[i][7] = v1.w;
        }
#pragma unroll
        for (int i = 0; i < 4; ++i) {
            const float* s = &Ws[rB[i] * SSTR + t4 * 8];
            float4 v0 = *(const float4*)s;
            float4 v1 = *(const float4*)(s + 4);
            bF[i][0] = v0.x; bF[i][1] = v0.y; bF[i][2] = v0.z; bF[i][3] = v0.w;
            bF[i][4] = v1.x; bF[i][5] = v1.y; bF[i][6] = v1.z; bF[i][7] = v1.w;
        }

        // ---- 4 k-steps x 2 m-frags x 4 n-frags = 32 MMAs
#pragma unroll
        for (int ks = 0; ks < 4; ++ks) {
            const int p0 = 2 * ks, p1 = 2 * ks + 1;
#pragma unroll
            for (int mf = 0; mf < 2; ++mf) {
                uint32_t a[4] = {
                    __float_as_uint(aF[mf * 2 + 0][p0]),   // a0: row g,    col 8ks+t4
                    __float_as_uint(aF[mf * 2 + 1][p0]),   // a1: row g+8,  col 8ks+t4
                    __float_as_uint(aF[mf * 2 + 0][p1]),   // a2: row g,    col 8ks+t4+4
                    __float_as_uint(aF[mf * 2 + 1][p1])};  // a3: row g+8,  col 8ks+t4+4
#pragma unroll
                for (int nf = 0; nf < 4; ++nf) {
                    uint32_t b[2] = {
                        __float_as_uint(bF[nf][p0]),       // b0: k 8ks+t4,   n g
                        __float_as_uint(bF[nf][p1])};      // b1: k 8ks+t4+4, n g
                    mma_tf32(acc[mf][nf], a, b);
                }
            }
        }
    }

    // ---- epilogue: C fragment layout c0/c1 -> (row g, cols 2t4, 2t4+1);
    //      c2/c3 -> row g+8.  Add bias, write fp32.
#pragma unroll
    for (int mf = 0; mf < 2; ++mf) {
        const int r0 = m0 + wm + mf * 16 + g;
#pragma unroll
        for (int nf = 0; nf < 4; ++nf) {
            const int col = n0 + wn + nf * 8 + t4 * 2;
            const float b0v = bias[col];
            const float b1v = bias[col + 1];
            float* p0 = &C[(size_t)r0 * EMB + col];
            p0[0] = acc[mf][nf][0] + b0v;
            p0[1] = acc[mf][nf][1] + b1v;
            float* p1 = &C[(size_t)(r0 + 8) * EMB + col];
            p1[0] = acc[mf][nf][2] + b0v;
            p1[1] = acc[mf][nf][3] + b1v;
        }
    }
}

// ---------------------------------------------------------------------------
// Flash-attention (fp32, online softmax) — unchanged from R2 (proven, 1.28ms).
// ---------------------------------------------------------------------------
#define AP 68
#define QS(r,c) Qs[(r) * AP + (c)]
#define KS(r,c) Ks[(r) * AP + (c)]
#define VS(r,c) Vs[(r) * AP + (c)]
#define PS(r,c) Ps[(r) * AP + (c)]

__global__ __launch_bounds__(256) void attn_kernel()
{
    extern __shared__ float sm[];
    float* Qs = sm;
    float* Ks = sm + 64 * AP;
    float* Vs = sm + 2 * 64 * AP;
    float* Ps = sm + 3 * 64 * AP;

    const int t   = threadIdx.x;
    const int tx  = t & 15;
    const int ty  = t >> 4;
    const int q0  = blockIdx.x * 64;
    const int h   = blockIdx.y;
    const int bb  = blockIdx.z;

    const size_t base = (size_t)bb * SEQ * EMB + h * DKH;

#pragma unroll
    for (int p = 0; p < 4; ++p) {
        const int r = p * 16 + (t >> 4);
        const int d = (t & 15) * 4;
        float4 v = *(const float4*)&g_q[base + (size_t)(q0 + r) * EMB + d];
        QS(r, d + 0) = v.x; QS(r, d + 1) = v.y;
        QS(r, d + 2) = v.z; QS(r, d + 3) = v.w;
    }

    float m_i[4], l_i[4], o[4][4];
#pragma unroll
    for (int i = 0; i < 4; ++i) {
        m_i[i] = -1e30f; l_i[i] = 0.f;
#pragma unroll
        for (int j = 0; j < 4; ++j) o[i][j] = 0.f;
    }

    const int ty4 = ty * 4, tx4 = tx * 4;

    for (int kt = 0; kt < SEQ / 64; ++kt) {
        __syncthreads();
#pragma unroll
        for (int p = 0; p < 4; ++p) {
            const int r = p * 16 + (t >> 4);
            const int d = (t & 15) * 4;
            const size_t gg = base + (size_t)(kt * 64 + r) * EMB + d;
            float4 kv = *(const float4*)&g_k[gg];
            float4 vv = *(const float4*)&g_v[gg];
            KS(r, d + 0) = kv.x; KS(r, d + 1) = kv.y;
            KS(r, d + 2) = kv.z; KS(r, d + 3) = kv.w;
            VS(r, d + 0) = vv.x; VS(r, d + 1) = vv.y;
            VS(r, d + 2) = vv.z; VS(r, d + 3) = vv.w;
        }
        __syncthreads();

        float s[4][4];
#pragma unroll
        for (int i = 0; i < 4; ++i)
#pragma unroll
            for (int j = 0; j < 4; ++j) s[i][j] = 0.f;

#pragma unroll 4
        for (int d4 = 0; d4 < 16; ++d4) {
            float4 qv[4], kv[4];
#pragma unroll
            for (int i = 0; i < 4; ++i) qv[i] = *(const float4*)&QS(ty4 + i, d4 * 4);
#pragma unroll
            for (int j = 0; j < 4; ++j) kv[j] = *(const float4*)&KS(tx4 + j, d4 * 4);
#pragma unroll
            for (int i = 0; i < 4; ++i)
#pragma unroll
                for (int j = 0; j < 4; ++j)
                    s[i][j] += qv[i].x * kv[j].x + qv[i].y * kv[j].y
                             + qv[i].z * kv[j].z + qv[i].w * kv[j].w;
        }

        const float scale = 0.125f;
#pragma unroll
        for (int i = 0; i < 4; ++i) {
            float rm = -1e30f;
#pragma unroll
            for (int j = 0; j < 4; ++j) {
                s[i][j] *= scale;
                rm = fmaxf(rm, s[i][j]);
            }
            rm = fmaxf(rm, __shfl_xor_sync(0xffffffffu, rm, 8));
            rm = fmaxf(rm, __shfl_xor_sync(0xffffffffu, rm, 4));
            rm = fmaxf(rm, __shfl_xor_sync(0xffffffffu, rm, 2));
            rm = fmaxf(rm, __shfl_xor_sync(0xffffffffu, rm, 1));

            const float mnew = fmaxf(m_i[i], rm);
            const float corr = __expf(m_i[i] - mnew);
            float rs = 0.f;
#pragma unroll
            for (int j = 0; j < 4; ++j) {
                s[i][j] = __expf(s[i][j] - mnew);
                rs += s[i][j];
            }
            rs += __shfl_xor_sync(0xffffffffu, rs, 8);
            rs += __shfl_xor_sync(0xffffffffu, rs, 4);
            rs += __shfl_xor_sync(0xffffffffu, rs, 2);
            rs += __shfl_xor_sync(0xffffffffu, rs, 1);

            l_i[i] = l_i[i] * corr + rs;
            m_i[i] = mnew;
#pragma unroll
            for (int j = 0; j < 4; ++j) o[i][j] *= corr;
        }

#pragma unroll
        for (int i = 0; i < 4; ++i)
            *(float4*)&PS(ty4 + i, tx4) = make_float4(s[i][0], s[i][1], s[i][2], s[i][3]);
        __syncthreads();

#pragma unroll 8
        for (int c = 0; c < 64; ++c) {
            float4 v4 = *(const float4*)&VS(c, tx4);
#pragma unroll
            for (int i = 0; i < 4; ++i) {
                const float pv = PS(ty4 + i, c);
                o[i][0] += pv * v4.x;
                o[i][1] += pv * v4.y;
                o[i][2] += pv * v4.z;
                o[i][3] += pv * v4.w;
            }
        }
    }

#pragma unroll
    for (int i = 0; i < 4; ++i) {
        const float inv = 1.f / l_i[i];
        const size_t row = base + (size_t)(q0 + ty4 + i) * EMB + tx4;
        *(float4*)&g_att[row] = make_float4(o[i][0] * inv, o[i][1] * inv,
                                            o[i][2] * inv, o[i][3] * inv);
    }
}

// ---------------------------------------------------------------------------
// Launch
// ---------------------------------------------------------------------------
extern "C" void kernel_launch(void* const* d_in, const int* in_sizes, int n_in,
                              void* d_out, int out_size)
{
    const float* q  = (const float*)d_in[0];
    const float* k  = (const float*)d_in[1];
    const float* v  = (const float*)d_in[2];
    const float* Wq = (const float*)d_in[3];
    const float* bq = (const float*)d_in[4];
    const float* Wk = (const float*)d_in[5];
    const float* bk = (const float*)d_in[6];
    const float* Wv = (const float*)d_in[7];
    const float* bv = (const float*)d_in[8];
    const float* Wo = (const float*)d_in[9];
    const float* bo = (const float*)d_in[10];
    float* out = (float*)d_out;

    float *gq, *gk, *gv, *ga;
    cudaGetSymbolAddress((void**)&gq, g_q);
    cudaGetSymbolAddress((void**)&gk, g_k);
    cudaGetSymbolAddress((void**)&gv, g_v);
    cudaGetSymbolAddress((void**)&ga, g_att);

    dim3 gg(EMB / BN, MTOT / BM);   // 12 x 32

    gemm_mma_kernel<<<gg, 256>>>(q, Wq, bq, gq);
    gemm_mma_kernel<<<gg, 256>>>(k, Wk, bk, gk);
    gemm_mma_kernel<<<gg, 256>>>(v, Wv, bv, gv);

    const int attn_smem = 4 * 64 * AP * (int)sizeof(float);   // 69632 B
    cudaFuncSetAttribute(attn_kernel, cudaFuncAttributeMaxDynamicSharedMemorySize, attn_smem);
    attn_kernel<<<dim3(SEQ / 64, HEADS, BATCH), 256, attn_smem>>>();

    gemm_mma_kernel<<<gg, 256>>>(ga, Wo, bo, out);
}